// round 6
// baseline (speedup 1.0000x reference)
#include <cuda_runtime.h>
#include <cstdint>

// ---------------------------------------------------------------------------
// Static problem dims
//   x: [64,128,48]  q/k/v conv -> [32,128,48]
//   attention: 16 batches (h in [0,8), j in [0,2)), q_len=3072, kv_len=5760, dph=4
//   out conv: [32,128,48] -> [64,128,48]
// ---------------------------------------------------------------------------
#define HW 6144            // 128*48
#define KV_LEN 5760        // 144*40
#define KV_PAIRS 2880
#define CHUNK_PAIRS 720    // 4 passes over kv
#define N_BATCH 16

typedef unsigned long long u64;

// scratch (allocation-free rule: __device__ globals)
__device__ __align__(16) float g_q[32 * HW];
__device__ __align__(16) float g_k[32 * HW];
__device__ __align__(16) float g_v[32 * HW];
__device__ __align__(16) float g_o[32 * HW];
// K gathered + pair-transposed: [n][p2][d*2+e]  (e = which element of the pair)
__device__ __align__(16) float g_ukT[N_BATCH * KV_PAIRS * 8];
// V gathered: [n][p][d]
__device__ __align__(16) float g_uv[N_BATCH * KV_LEN * 4];

// ---------------- packed f32x2 helpers (FFMA2 path) ------------------------
__device__ __forceinline__ u64 pk2(float lo, float hi) {
    u64 r; asm("mov.b64 %0, {%1, %2};" : "=l"(r) : "f"(lo), "f"(hi)); return r;
}
__device__ __forceinline__ void upk2(u64 v, float& a, float& b) {
    asm("mov.b64 {%0, %1}, %2;" : "=f"(a), "=f"(b) : "l"(v));
}
__device__ __forceinline__ void upk2u(u64 v, unsigned& a, unsigned& b) {
    asm("mov.b64 {%0, %1}, %2;" : "=r"(a), "=r"(b) : "l"(v));
}
__device__ __forceinline__ u64 f2fma(u64 a, u64 b, u64 c) {
    u64 d; asm("fma.rn.f32x2 %0, %1, %2, %3;" : "=l"(d) : "l"(a), "l"(b), "l"(c)); return d;
}
__device__ __forceinline__ u64 f2add(u64 a, u64 b) {
    u64 d; asm("add.rn.f32x2 %0, %1, %2;" : "=l"(d) : "l"(a), "l"(b)); return d;
}
__device__ __forceinline__ u64 f2mul(u64 a, u64 b) {
    u64 d; asm("mul.rn.f32x2 %0, %1, %2;" : "=l"(d) : "l"(a), "l"(b)); return d;
}

// ---------------------------------------------------------------------------
// Generic 3x3 same-conv:  out[oc] = (sum_c sum_tap in[c]*w[oc][c][tap] + b[oc])*scale
// Block: 192 threads, tile = 8 rows x 48 cols, 16 output channels, 2 px/thread.
// ---------------------------------------------------------------------------
__device__ __forceinline__ void conv3x3_body(
    const float* __restrict__ in, const float* __restrict__ w,
    const float* __restrict__ bias, float* __restrict__ out,
    int Cin, int ocbase, float scale)
{
    __shared__ __align__(16) float sx[8 * 10 * 50];   // [cc][ry][cx]
    __shared__ __align__(16) float sw[16 * 8 * 9];    // [oc][cc][tap]
    const int t   = threadIdx.x;
    const int col = t % 48;
    const int rq  = t / 48;              // 0..3 -> rows rq and rq+4
    const int R0  = blockIdx.x * 8;

    float acc0[16], acc1[16];
#pragma unroll
    for (int i = 0; i < 16; i++) { acc0[i] = 0.f; acc1[i] = 0.f; }

    const int nch = Cin >> 3;
    for (int ch = 0; ch < nch; ch++) {
        // stage x tile (with halo, zero-padded)
        for (int i = t; i < 4000; i += 192) {
            int cc = i / 500, rem = i - cc * 500;
            int ry = rem / 50, cx = rem - ry * 50;
            int gr = R0 - 1 + ry, gc = cx - 1;
            float v = 0.f;
            if ((unsigned)gr < 128u && (unsigned)gc < 48u)
                v = in[(ch * 8 + cc) * HW + gr * 48 + gc];
            sx[i] = v;
        }
        // stage weights
        for (int i = t; i < 1152; i += 192) {
            int oc = i / 72, rem = i - oc * 72;
            sw[i] = w[(ocbase + oc) * Cin * 9 + ch * 72 + rem];
        }
        __syncthreads();
        for (int cc = 0; cc < 8; cc++) {
#pragma unroll
            for (int tap = 0; tap < 9; tap++) {
                int ky = tap / 3, kx = tap - ky * 3;
                float x0 = sx[cc * 500 + (rq + ky) * 50 + col + kx];
                float x1 = sx[cc * 500 + (rq + 4 + ky) * 50 + col + kx];
#pragma unroll
                for (int oc = 0; oc < 16; oc++) {
                    float wv = sw[oc * 72 + cc * 9 + tap];
                    acc0[oc] += x0 * wv;
                    acc1[oc] += x1 * wv;
                }
            }
        }
        __syncthreads();
    }
#pragma unroll
    for (int oc = 0; oc < 16; oc++) {
        float b = bias ? bias[ocbase + oc] : 0.f;
        out[(ocbase + oc) * HW + (R0 + rq) * 48 + col]     = (acc0[oc] + b) * scale;
        out[(ocbase + oc) * HW + (R0 + rq + 4) * 48 + col] = (acc1[oc] + b) * scale;
    }
}

// fused q/k/v conv: gridDim.y = 6 (q0,q1,k0,k1,v0,v1). q gets 0.5*log2e folded in.
__global__ __launch_bounds__(192) void conv_qkv_kernel(
    const float* __restrict__ x,
    const float* __restrict__ wq, const float* __restrict__ bq,
    const float* __restrict__ wk, const float* __restrict__ bk,
    const float* __restrict__ wv, const float* __restrict__ bv)
{
    int sel    = blockIdx.y >> 1;
    int ocbase = (blockIdx.y & 1) * 16;
    const float* w = sel == 0 ? wq : (sel == 1 ? wk : wv);
    const float* b = sel == 0 ? bq : (sel == 1 ? bk : bv);
    float* out     = sel == 0 ? g_q : (sel == 1 ? g_k : g_v);
    float scale    = sel == 0 ? 0.72134752044448170f : 1.0f;  // 0.5 * log2(e)
    conv3x3_body(x, w, b, out, 64, ocbase, scale);
}

__global__ __launch_bounds__(192) void conv_out_kernel(
    const float* __restrict__ wo, float* __restrict__ out)
{
    conv3x3_body(g_o, wo, nullptr, out, 32, blockIdx.y * 16, 1.0f);
}

// ---------------------------------------------------------------------------
// Gather: reproduce torch.as_strided exactly.
//   flat f = h*24576 + d*6144 + j*24 + m0*48 + m1   (nH=1 -> i=0)
//   decomposed against padded storage [8,4,144,64] (strides 36864/9216/64/1)
// ---------------------------------------------------------------------------
__global__ __launch_bounds__(256) void gather_kernel()
{
    int idx = blockIdx.x * 256 + threadIdx.x;       // exactly 16*5760 threads
    int n = idx / KV_LEN, p = idx - n * KV_LEN;
    int h = n >> 1, j = n & 1;
    int m0 = p / 40, m1 = p - m0 * 40;
    int fbase = h * 24576 + j * 24 + m0 * 48 + m1;

    float kv[4], vv[4];
#pragma unroll
    for (int d = 0; d < 4; d++) {
        int f   = fbase + d * 6144;
        int hp  = f / 36864;  int rem = f - hp * 36864;
        int dp  = rem / 9216; rem -= dp * 9216;
        int r   = rem >> 6;   int c = rem & 63;
        int rr  = r - 8, cc = c - 8;
        float kvv = 0.f, vvv = 0.f;
        if ((unsigned)rr < 128u && (unsigned)cc < 48u) {
            int off = (hp * 4 + dp) * HW + rr * 48 + cc;
            kvv = g_k[off];
            vvv = g_v[off];
        }
        kv[d] = kvv; vv[d] = vvv;
    }
    *(float4*)&g_uv[(n * KV_LEN + p) * 4] = make_float4(vv[0], vv[1], vv[2], vv[3]);
    int p2 = p >> 1, e = p & 1;
    float* kb = &g_ukT[(n * KV_PAIRS + p2) * 8 + e];
    kb[0] = kv[0]; kb[2] = kv[1]; kb[4] = kv[2]; kb[6] = kv[3];
}

// ---------------------------------------------------------------------------
// Attention: 384 CTAs x 128 thr. One thread = one query. 4 smem passes over kv.
// Logits already base-2 (scale folded into q). No max-subtraction needed.
// exp2 via magic-round + deg-5 poly, everything in packed f32x2 (FFMA2).
// ---------------------------------------------------------------------------
__global__ __launch_bounds__(128) void attn_kernel()
{
    __shared__ __align__(16) float sk[CHUNK_PAIRS * 8];
    __shared__ __align__(16) float sv[CHUNK_PAIRS * 8];

    const int bid   = blockIdx.x;
    const int n     = bid & 15;
    const int chunk = bid >> 4;        // 0..23
    const int tid   = threadIdx.x;
    const int qi    = chunk * 128 + tid;
    const int h = n >> 1, j = n & 1;
    const int q0 = qi / 24, q1 = qi - q0 * 24;
    const int qoff = q0 * 48 + j * 24 + q1;

    float qv0 = g_q[(h * 4 + 0) * HW + qoff];
    float qv1 = g_q[(h * 4 + 1) * HW + qoff];
    float qv2 = g_q[(h * 4 + 2) * HW + qoff];
    float qv3 = g_q[(h * 4 + 3) * HW + qoff];
    const u64 qp0 = pk2(qv0, qv0), qp1 = pk2(qv1, qv1);
    const u64 qp2 = pk2(qv2, qv2), qp3 = pk2(qv3, qv3);

    const u64 C5   = pk2(1.33335581e-3f, 1.33335581e-3f);
    const u64 C4   = pk2(9.61812911e-3f, 9.61812911e-3f);
    const u64 C3   = pk2(5.55041087e-2f, 5.55041087e-2f);
    const u64 C2   = pk2(2.40226507e-1f, 2.40226507e-1f);
    const u64 C1   = pk2(6.93147181e-1f, 6.93147181e-1f);
    const u64 ONE2 = pk2(1.0f, 1.0f);
    const u64 MG   = pk2(12582912.0f, 12582912.0f);     // 1.5 * 2^23
    const u64 NMG  = pk2(-12582912.0f, -12582912.0f);
    const u64 NONE = pk2(-1.0f, -1.0f);

    u64 acc01 = 0ull, acc23 = 0ull, den = 0ull;   // bit-zero == (0.f, 0.f)

    for (int pass = 0; pass < 4; pass++) {
        const float4* gk4 = (const float4*)&g_ukT[(n * KV_PAIRS + pass * CHUNK_PAIRS) * 8];
        const float4* gv4 = (const float4*)&g_uv[(n * KV_LEN + pass * (CHUNK_PAIRS * 2)) * 4];
        __syncthreads();
        for (int i = tid; i < CHUNK_PAIRS * 2; i += 128) {
            ((float4*)sk)[i] = gk4[i];
            ((float4*)sv)[i] = gv4[i];
        }
        __syncthreads();
#pragma unroll 2
        for (int p2 = 0; p2 < CHUNK_PAIRS; p2++) {
            ulonglong2 A  = *(const ulonglong2*)&sk[p2 * 8];      // (k0_0,k1_0) (k0_1,k1_1)
            ulonglong2 Bk = *(const ulonglong2*)&sk[p2 * 8 + 4];  // (k0_2,k1_2) (k0_3,k1_3)
            ulonglong2 V0 = *(const ulonglong2*)&sv[p2 * 8];      // v_elem0: (d0,d1)(d2,d3)
            ulonglong2 V1 = *(const ulonglong2*)&sv[p2 * 8 + 4];  // v_elem1

            u64 l = f2mul(qp0, A.x);
            l = f2fma(qp1, A.y, l);
            l = f2fma(qp2, Bk.x, l);
            l = f2fma(qp3, Bk.y, l);

            // e = 2^l : round, poly on frac, exponent via bit add
            u64 r  = f2add(l, MG);
            u64 rr = f2add(r, NMG);
            u64 f  = f2fma(rr, NONE, l);        // frac in [-0.5, 0.5]
            u64 pq = f2fma(C5, f, C4);
            pq = f2fma(pq, f, C3);
            pq = f2fma(pq, f, C2);
            pq = f2fma(pq, f, C1);
            pq = f2fma(pq, f, ONE2);
            unsigned r0, r1, pb0, pb1;
            upk2u(r, r0, r1);
            upk2u(pq, pb0, pb1);
            float e0 = __uint_as_float(pb0 + (r0 << 23));
            float e1 = __uint_as_float(pb1 + (r1 << 23));

            den = f2add(den, pk2(e0, e1));
            u64 e0p = pk2(e0, e0), e1p = pk2(e1, e1);
            acc01 = f2fma(e0p, V0.x, acc01);
            acc23 = f2fma(e0p, V0.y, acc23);
            acc01 = f2fma(e1p, V1.x, acc01);
            acc23 = f2fma(e1p, V1.y, acc23);
        }
    }

    float a0, a1, a2, a3, d0, d1;
    upk2(acc01, a0, a1);
    upk2(acc23, a2, a3);
    upk2(den, d0, d1);
    float inv = 1.0f / (d0 + d1);
    g_o[(h * 4 + 0) * HW + qoff] = a0 * inv;
    g_o[(h * 4 + 1) * HW + qoff] = a1 * inv;
    g_o[(h * 4 + 2) * HW + qoff] = a2 * inv;
    g_o[(h * 4 + 3) * HW + qoff] = a3 * inv;
}

// ---------------------------------------------------------------------------
extern "C" void kernel_launch(void* const* d_in, const int* in_sizes, int n_in,
                              void* d_out, int out_size)
{
    const float* x  = (const float*)d_in[0];
    const float* wq = (const float*)d_in[1];
    const float* bq = (const float*)d_in[2];
    const float* wk = (const float*)d_in[3];
    const float* bk = (const float*)d_in[4];
    const float* wv = (const float*)d_in[5];
    const float* bv = (const float*)d_in[6];
    const float* wo = (const float*)d_in[7];
    float* out = (float*)d_out;

    conv_qkv_kernel<<<dim3(16, 6), 192>>>(x, wq, bq, wk, bk, wv, bv);
    gather_kernel<<<(N_BATCH * KV_LEN) / 256, 256>>>();
    attn_kernel<<<N_BATCH * 24, 128>>>();
    conv_out_kernel<<<dim3(16, 4), 192>>>(wo, out);
}

// round 8
// speedup vs baseline: 1.0461x; 1.0461x over previous
#include <cuda_runtime.h>
#include <cstdint>

// ---------------------------------------------------------------------------
// Static problem dims
//   x: [64,128,48]  q/k/v conv -> [32,128,48]
//   attention: 16 batches (h in [0,8), j in [0,2)), q_len=3072, kv_len=5760, dph=4
//   out conv: [32,128,48] -> [64,128,48]
// ---------------------------------------------------------------------------
#define HW 6144            // 128*48
#define KV_LEN 5760        // 144*40
#define KV_PAIRS 2880
#define SPLIT_PAIRS 1440   // kv pairs per split (2 splits)
#define CHUNK_PAIRS 360    // smem chunk: 4 passes per split
#define N_BATCH 16
#define NQ_TOT 49152       // 16 * 3072 queries

typedef unsigned long long u64;

// scratch (allocation-free rule: __device__ globals)
__device__ __align__(16) float g_q[32 * HW];
__device__ __align__(16) float g_k[32 * HW];
__device__ __align__(16) float g_v[32 * HW];
__device__ __align__(16) float g_o[32 * HW];
// K gathered + pair-transposed: [n][p2][d*2+e]
__device__ __align__(16) float g_ukT[N_BATCH * KV_PAIRS * 8];
// V gathered: [n][p][d]
__device__ __align__(16) float g_uv[N_BATCH * KV_LEN * 4];
// attention partials: [split][query][a0 a1 a2 a3 den pad pad pad]
__device__ __align__(16) float g_part[2 * NQ_TOT * 8];

// ---------------- packed f32x2 helpers (FFMA2 path) ------------------------
__device__ __forceinline__ u64 pk2(float lo, float hi) {
    u64 r; asm("mov.b64 %0, {%1, %2};" : "=l"(r) : "f"(lo), "f"(hi)); return r;
}
__device__ __forceinline__ void upk2(u64 v, float& a, float& b) {
    asm("mov.b64 {%0, %1}, %2;" : "=f"(a), "=f"(b) : "l"(v));
}
__device__ __forceinline__ void upk2u(u64 v, unsigned& a, unsigned& b) {
    asm("mov.b64 {%0, %1}, %2;" : "=r"(a), "=r"(b) : "l"(v));
}
__device__ __forceinline__ u64 f2fma(u64 a, u64 b, u64 c) {
    u64 d; asm("fma.rn.f32x2 %0, %1, %2, %3;" : "=l"(d) : "l"(a), "l"(b), "l"(c)); return d;
}
__device__ __forceinline__ u64 f2add(u64 a, u64 b) {
    u64 d; asm("add.rn.f32x2 %0, %1, %2;" : "=l"(d) : "l"(a), "l"(b)); return d;
}
__device__ __forceinline__ u64 f2mul(u64 a, u64 b) {
    u64 d; asm("mul.rn.f32x2 %0, %1, %2;" : "=l"(d) : "l"(a), "l"(b)); return d;
}

// ---------------------------------------------------------------------------
// 3x3 same-conv, high-parallelism variant:
//   block = 192 threads = 4 rows x 48 cols, 1 px/thread, 8 output channels.
//   grid.x = 32 row-tiles (4 rows each).
// ---------------------------------------------------------------------------
__device__ __forceinline__ void conv3x3_body(
    const float* __restrict__ in, const float* __restrict__ w,
    const float* __restrict__ bias, float* __restrict__ out,
    int Cin, int ocbase, float scale)
{
    __shared__ __align__(16) float sx[8 * 6 * 50];   // [cc][ry][cx] (6 rows halo)
    __shared__ __align__(16) float sw[8 * 8 * 9];    // [oc][cc][tap]
    const int t   = threadIdx.x;
    const int col = t % 48;
    const int rq  = t / 48;              // 0..3
    const int R0  = blockIdx.x * 4;

    float acc[8];
#pragma unroll
    for (int i = 0; i < 8; i++) acc[i] = 0.f;

    const int nch = Cin >> 3;
    for (int ch = 0; ch < nch; ch++) {
        // stage x tile (with halo, zero-padded)
        for (int i = t; i < 2400; i += 192) {
            int cc = i / 300, rem = i - cc * 300;
            int ry = rem / 50, cx = rem - ry * 50;
            int gr = R0 - 1 + ry, gc = cx - 1;
            float v = 0.f;
            if ((unsigned)gr < 128u && (unsigned)gc < 48u)
                v = in[(ch * 8 + cc) * HW + gr * 48 + gc];
            sx[i] = v;
        }
        // stage weights: [oc][cc][tap], 8 oc x 72
        for (int i = t; i < 576; i += 192) {
            int oc = i / 72, rem = i - oc * 72;
            sw[i] = w[(ocbase + oc) * Cin * 9 + ch * 72 + rem];
        }
        __syncthreads();
        for (int cc = 0; cc < 8; cc++) {
#pragma unroll
            for (int tap = 0; tap < 9; tap++) {
                int ky = tap / 3, kx = tap - ky * 3;
                float x = sx[cc * 300 + (rq + ky) * 50 + col + kx];
#pragma unroll
                for (int oc = 0; oc < 8; oc++)
                    acc[oc] += x * sw[oc * 72 + cc * 9 + tap];
            }
        }
        __syncthreads();
    }
#pragma unroll
    for (int oc = 0; oc < 8; oc++) {
        float b = bias ? bias[ocbase + oc] : 0.f;
        out[(ocbase + oc) * HW + (R0 + rq) * 48 + col] = (acc[oc] + b) * scale;
    }
}

// fused q/k/v conv: grid (32, 12). y: sel = y>>2 (q,k,v), ocgroup = y&3.
// q gets 0.5*log2(e) folded in (logits become base-2).
__global__ __launch_bounds__(192) void conv_qkv_kernel(
    const float* __restrict__ x,
    const float* __restrict__ wq, const float* __restrict__ bq,
    const float* __restrict__ wk, const float* __restrict__ bk,
    const float* __restrict__ wv, const float* __restrict__ bv)
{
    int sel    = blockIdx.y >> 2;
    int ocbase = (blockIdx.y & 3) * 8;
    const float* w = sel == 0 ? wq : (sel == 1 ? wk : wv);
    const float* b = sel == 0 ? bq : (sel == 1 ? bk : bv);
    float* out     = sel == 0 ? g_q : (sel == 1 ? g_k : g_v);
    float scale    = sel == 0 ? 0.72134752044448170f : 1.0f;  // 0.5 * log2(e)
    conv3x3_body(x, w, b, out, 64, ocbase, scale);
}

// out conv: grid (32, 8)
__global__ __launch_bounds__(192) void conv_out_kernel(
    const float* __restrict__ wo, float* __restrict__ out)
{
    conv3x3_body(g_o, wo, nullptr, out, 32, blockIdx.y * 8, 1.0f);
}

// ---------------------------------------------------------------------------
// Gather: reproduce torch.as_strided exactly.
//   flat f = h*24576 + d*6144 + j*24 + m0*48 + m1   (nH=1 -> i=0)
//   decomposed against padded storage [8,4,144,64] (strides 36864/9216/64/1)
// ---------------------------------------------------------------------------
__global__ __launch_bounds__(256) void gather_kernel()
{
    int idx = blockIdx.x * 256 + threadIdx.x;       // exactly 16*5760 threads
    int n = idx / KV_LEN, p = idx - n * KV_LEN;
    int h = n >> 1, j = n & 1;
    int m0 = p / 40, m1 = p - m0 * 40;
    int fbase = h * 24576 + j * 24 + m0 * 48 + m1;

    float kv[4], vv[4];
#pragma unroll
    for (int d = 0; d < 4; d++) {
        int f   = fbase + d * 6144;
        int hp  = f / 36864;  int rem = f - hp * 36864;
        int dp  = rem / 9216; rem -= dp * 9216;
        int r   = rem >> 6;   int c = rem & 63;
        int rr  = r - 8, cc = c - 8;
        float kvv = 0.f, vvv = 0.f;
        if ((unsigned)rr < 128u && (unsigned)cc < 48u) {
            int off = (hp * 4 + dp) * HW + rr * 48 + cc;
            kvv = g_k[off];
            vvv = g_v[off];
        }
        kv[d] = kvv; vv[d] = vvv;
    }
    *(float4*)&g_uv[(n * KV_LEN + p) * 4] = make_float4(vv[0], vv[1], vv[2], vv[3]);
    int p2 = p >> 1, e = p & 1;
    float* kb = &g_ukT[(n * KV_PAIRS + p2) * 8 + e];
    kb[0] = kv[0]; kb[2] = kv[1]; kb[4] = kv[2]; kb[6] = kv[3];
}

// ---------------------------------------------------------------------------
// Attention: grid (16 batches, 24 q-chunks, 2 kv-splits) x 128 thr.
// One thread = one query; each CTA covers half the kv via 4 smem passes.
// No max-subtraction (logits bounded, fp32 range trivially safe) -> splits
// are purely additive: each (query, split) writes an independent partial.
// exp2 via magic-round + deg-5 poly, all on packed f32x2 (FFMA2).
// ---------------------------------------------------------------------------
__global__ __launch_bounds__(128, 5) void attn_kernel()
{
    __shared__ __align__(16) float sk[CHUNK_PAIRS * 8];
    __shared__ __align__(16) float sv[CHUNK_PAIRS * 8];

    const int n     = blockIdx.x;
    const int chunk = blockIdx.y;
    const int s     = blockIdx.z;
    const int tid   = threadIdx.x;
    const int qi    = chunk * 128 + tid;
    const int h = n >> 1, j = n & 1;
    const int q0 = qi / 24, q1 = qi - q0 * 24;
    const int qoff = q0 * 48 + j * 24 + q1;

    float qv0 = g_q[(h * 4 + 0) * HW + qoff];
    float qv1 = g_q[(h * 4 + 1) * HW + qoff];
    float qv2 = g_q[(h * 4 + 2) * HW + qoff];
    float qv3 = g_q[(h * 4 + 3) * HW + qoff];
    const u64 qp0 = pk2(qv0, qv0), qp1 = pk2(qv1, qv1);
    const u64 qp2 = pk2(qv2, qv2), qp3 = pk2(qv3, qv3);

    const u64 C5   = pk2(1.33335581e-3f, 1.33335581e-3f);
    const u64 C4   = pk2(9.61812911e-3f, 9.61812911e-3f);
    const u64 C3   = pk2(5.55041087e-2f, 5.55041087e-2f);
    const u64 C2   = pk2(2.40226507e-1f, 2.40226507e-1f);
    const u64 C1   = pk2(6.93147181e-1f, 6.93147181e-1f);
    const u64 ONE2 = pk2(1.0f, 1.0f);
    const u64 MG   = pk2(12582912.0f, 12582912.0f);     // 1.5 * 2^23
    const u64 NMG  = pk2(-12582912.0f, -12582912.0f);
    const u64 NONE = pk2(-1.0f, -1.0f);

    u64 acc01 = 0ull, acc23 = 0ull, den = 0ull;   // bit-zero == (0.f, 0.f)

    const int pbase = s * SPLIT_PAIRS;
    for (int pass = 0; pass < 4; pass++) {
        const int P = pbase + pass * CHUNK_PAIRS;
        const float4* gk4 = (const float4*)&g_ukT[(n * KV_PAIRS + P) * 8];
        const float4* gv4 = (const float4*)&g_uv[(n * KV_LEN + 2 * P) * 4];
        __syncthreads();
        for (int i = tid; i < CHUNK_PAIRS * 2; i += 128) {
            ((float4*)sk)[i] = gk4[i];
            ((float4*)sv)[i] = gv4[i];
        }
        __syncthreads();
#pragma unroll 2
        for (int p2 = 0; p2 < CHUNK_PAIRS; p2++) {
            ulonglong2 A  = *(const ulonglong2*)&sk[p2 * 8];      // (k0_0,k1_0)(k0_1,k1_1)
            ulonglong2 Bk = *(const ulonglong2*)&sk[p2 * 8 + 4];  // (k0_2,k1_2)(k0_3,k1_3)
            ulonglong2 V0 = *(const ulonglong2*)&sv[p2 * 8];      // v_elem0: (d0,d1)(d2,d3)
            ulonglong2 V1 = *(const ulonglong2*)&sv[p2 * 8 + 4];  // v_elem1

            u64 l = f2mul(qp0, A.x);
            l = f2fma(qp1, A.y, l);
            l = f2fma(qp2, Bk.x, l);
            l = f2fma(qp3, Bk.y, l);

            // e = 2^l : round, poly on frac, exponent via bit add
            u64 r  = f2add(l, MG);
            u64 rr = f2add(r, NMG);
            u64 f  = f2fma(rr, NONE, l);        // frac in [-0.5, 0.5]
            u64 pq = f2fma(C5, f, C4);
            pq = f2fma(pq, f, C3);
            pq = f2fma(pq, f, C2);
            pq = f2fma(pq, f, C1);
            pq = f2fma(pq, f, ONE2);
            unsigned r0, r1, pb0, pb1;
            upk2u(r, r0, r1);
            upk2u(pq, pb0, pb1);
            float e0 = __uint_as_float(pb0 + (r0 << 23));
            float e1 = __uint_as_float(pb1 + (r1 << 23));

            den = f2add(den, pk2(e0, e1));
            u64 e0p = pk2(e0, e0), e1p = pk2(e1, e1);
            acc01 = f2fma(e0p, V0.x, acc01);
            acc23 = f2fma(e0p, V0.y, acc23);
            acc01 = f2fma(e1p, V1.x, acc01);
            acc23 = f2fma(e1p, V1.y, acc23);
        }
    }

    float a0, a1, a2, a3, d0, d1;
    upk2(acc01, a0, a1);
    upk2(acc23, a2, a3);
    upk2(den, d0, d1);
    int p = (s * NQ_TOT + n * 3072 + qi) * 8;
    *(float4*)&g_part[p] = make_float4(a0, a1, a2, a3);
    g_part[p + 4] = d0 + d1;
}

// ---------------------------------------------------------------------------
// Merge the 2 kv-split partials, normalize, scatter into g_o layout.
// ---------------------------------------------------------------------------
__global__ __launch_bounds__(256) void norm_kernel()
{
    int q = blockIdx.x * 256 + threadIdx.x;     // 49152 threads
    float4 A0 = *(const float4*)&g_part[q * 8];
    float  d0 = g_part[q * 8 + 4];
    float4 A1 = *(const float4*)&g_part[(NQ_TOT + q) * 8];
    float  d1 = g_part[(NQ_TOT + q) * 8 + 4];
    float inv = 1.0f / (d0 + d1);

    int n = q / 3072, qi = q - n * 3072;
    int h = n >> 1, j = n & 1;
    int q0 = qi / 24, q1 = qi - q0 * 24;
    int qoff = q0 * 48 + j * 24 + q1;
    g_o[(h * 4 + 0) * HW + qoff] = (A0.x + A1.x) * inv;
    g_o[(h * 4 + 1) * HW + qoff] = (A0.y + A1.y) * inv;
    g_o[(h * 4 + 2) * HW + qoff] = (A0.z + A1.z) * inv;
    g_o[(h * 4 + 3) * HW + qoff] = (A0.w + A1.w) * inv;
}

// ---------------------------------------------------------------------------
extern "C" void kernel_launch(void* const* d_in, const int* in_sizes, int n_in,
                              void* d_out, int out_size)
{
    const float* x  = (const float*)d_in[0];
    const float* wq = (const float*)d_in[1];
    const float* bq = (const float*)d_in[2];
    const float* wk = (const float*)d_in[3];
    const float* bk = (const float*)d_in[4];
    const float* wv = (const float*)d_in[5];
    const float* bv = (const float*)d_in[6];
    const float* wo = (const float*)d_in[7];
    float* out = (float*)d_out;

    conv_qkv_kernel<<<dim3(32, 12), 192>>>(x, wq, bq, wk, bk, wv, bv);
    gather_kernel<<<(N_BATCH * KV_LEN) / 256, 256>>>();
    attn_kernel<<<dim3(16, 24, 2), 128>>>();
    norm_kernel<<<NQ_TOT / 256, 256>>>();
    conv_out_kernel<<<dim3(32, 8), 192>>>(wo, out);
}